// round 16
// baseline (speedup 1.0000x reference)
#include <cuda_runtime.h>
#include <cuda_fp16.h>
#include <math_constants.h>
#include <cstdint>

// Problem constants
#define BB   2
#define NN   4096
#define MM   4096
#define DD   512
#define HH   8
#define PP   64
#define RR   (BB * NN)

// ---------------- scratch (fp16) ----------------
__device__ __half g_q[(size_t)RR * DD];
__device__ __half g_k[(size_t)RR * DD];
__device__ __half g_vt[(size_t)RR * DD];    // V transposed: [b][h][p][m]
__device__ __half g_xq[(size_t)RR * DD];
__device__ __half g_xk[(size_t)RR * DD];
__device__ __half g_xv[(size_t)RR * DD];
__device__ __half g_wqt[(size_t)DD * DD];   // W transposed: Wt[n][k]
__device__ __half g_wkt[(size_t)DD * DD];
__device__ __half g_wvt[(size_t)DD * DD];

// ---------------- helpers ----------------
__device__ __forceinline__ uint32_t smem_u32(const void* p) {
    uint32_t a;
    asm("{ .reg .u64 t; cvta.to.shared.u64 t, %1; cvt.u32.u64 %0, t; }" : "=r"(a) : "l"(p));
    return a;
}
#define CP_ASYNC16(dst_u32, src) \
    asm volatile("cp.async.cg.shared.global [%0], [%1], 16;" :: "r"(dst_u32), "l"(src))
#define CP_COMMIT() asm volatile("cp.async.commit_group;" ::: "memory")
#define CP_WAIT1()  asm volatile("cp.async.wait_group 1;" ::: "memory")
#define CP_WAIT0()  asm volatile("cp.async.wait_group 0;" ::: "memory")

// fp16: D(16x8) += A(16x16) @ B(16x8), fp32 accum
__device__ __forceinline__ void mma16(float c[4], uint32_t a0, uint32_t a1,
                                      uint32_t a2, uint32_t a3,
                                      uint32_t b0, uint32_t b1) {
    asm volatile(
        "mma.sync.aligned.m16n8k16.row.col.f32.f16.f16.f32 "
        "{%0,%1,%2,%3}, {%4,%5,%6,%7}, {%8,%9}, {%0,%1,%2,%3};\n"
        : "+f"(c[0]), "+f"(c[1]), "+f"(c[2]), "+f"(c[3])
        : "r"(a0), "r"(a1), "r"(a2), "r"(a3), "r"(b0), "r"(b1));
}
__device__ __forceinline__ uint32_t packh2(float lo, float hi) {
    __half2 h = __floats2half2_rn(lo, hi);
    return *reinterpret_cast<uint32_t*>(&h);
}
__device__ __forceinline__ uint32_t exph2(float lo, float hi) {
    __half2 h = h2exp2(__floats2half2_rn(lo, hi));
    return *reinterpret_cast<uint32_t*>(&h);
}

// ================= Convert passes (fused over z) =================
__global__ __launch_bounds__(256) void f2h3_kernel(
    const float4* __restrict__ s0, const float4* __restrict__ s1,
    const float4* __restrict__ s2,
    __half* __restrict__ d0, __half* __restrict__ d1, __half* __restrict__ d2,
    int n4)
{
    const int z = blockIdx.z;
    const float4* src = z == 0 ? s0 : (z == 1 ? s1 : s2);
    __half*       dst = z == 0 ? d0 : (z == 1 ? d1 : d2);
    int i = blockIdx.x * blockDim.x + threadIdx.x;
    int stride = gridDim.x * blockDim.x;
    for (; i < n4; i += stride) {
        float4 v = src[i];
        uint2 o;
        o.x = packh2(v.x, v.y);
        o.y = packh2(v.z, v.w);
        *(uint2*)(dst + (size_t)i * 4) = o;
    }
}
// W[k][n] fp32 -> Wt[n][k] fp16, 32x32 smem tiles, z selects matrix
__global__ __launch_bounds__(256) void wt_h3_kernel(
    const float* __restrict__ W0, const float* __restrict__ W1,
    const float* __restrict__ W2,
    __half* __restrict__ T0, __half* __restrict__ T1, __half* __restrict__ T2)
{
    const int z = blockIdx.z;
    const float* W  = z == 0 ? W0 : (z == 1 ? W1 : W2);
    __half*      Wt = z == 0 ? T0 : (z == 1 ? T1 : T2);
    __shared__ float t[32][33];
    const int tx = threadIdx.x, ty = threadIdx.y;   // block (32,8)
    const int bx = blockIdx.x * 32;   // n base
    const int by = blockIdx.y * 32;   // k base
#pragma unroll
    for (int j = 0; j < 32; j += 8)
        t[ty + j][tx] = W[(size_t)(by + ty + j) * DD + bx + tx];
    __syncthreads();
#pragma unroll
    for (int j = 0; j < 32; j += 8)
        Wt[(size_t)(bx + ty + j) * DD + by + tx] = __float2half(t[tx][ty + j]);
}

// ================= Projection GEMM via mma fp16 =================
// Y[8192,512] = X @ W + b; tile M=128 x N=128, 256 thr (8 warps):
// warp w -> rows (w&3)*32, cols (w>>2)*64. K-chunks 64, cp.async dbl-buffered.
// z==2 (V) writes output TRANSPOSED: Vt[((b*8+h)*64+p)*M + m].
#define PSTR 72    // halfs, 144B rows
#define POFF_X0 0
#define POFF_X1 (128 * PSTR)
#define POFF_W0 (2 * 128 * PSTR)
#define POFF_W1 (3 * 128 * PSTR)
#define PROJ_SMEM_BYTES (4 * 128 * PSTR * 2)   // 73728 B
#define NCH 8

__global__ __launch_bounds__(256) void proj_mma_kernel(
    const __half* __restrict__ Xq, const __half* __restrict__ Xk, const __half* __restrict__ Xv,
    const __half* __restrict__ Wqt, const __half* __restrict__ Wkt, const __half* __restrict__ Wvt,
    const float* __restrict__ bq, const float* __restrict__ bk, const float* __restrict__ bv,
    __half* __restrict__ Yq, __half* __restrict__ Yk, __half* __restrict__ Yv)
{
    extern __shared__ __half smh[];
    const uint32_t smbase = smem_u32(smh);

    const int z = blockIdx.z;
    const __half* X    = z == 0 ? Xq : (z == 1 ? Xk : Xv);
    const __half* Wt   = z == 0 ? Wqt : (z == 1 ? Wkt : Wvt);
    const float*  bias = z == 0 ? bq : (z == 1 ? bk : bv);
    __half*       Y    = z == 0 ? Yq : (z == 1 ? Yk : Yv);
    // Q gets 1/sqrt(P) * log2(e) folded in (softmax done base-2 downstream).
    const float   sc   = z == 0 ? 0.125f * 1.4426950408889634f : 1.0f;

    const int tid  = threadIdx.x;
    const int lane = tid & 31;
    const int w    = tid >> 5;      // 0..7
    const int wr   = w & 3;         // row block
    const int wc   = w >> 2;        // col block
    const int gid  = lane >> 2;
    const int tig  = lane & 3;
    const int rb   = blockIdx.y * 128;
    const int cb   = blockIdx.x * 128;

    // prefetch chunk 0
    {
        const __half* Xc = X + (size_t)rb * DD;
        const __half* Wc = Wt + (size_t)cb * DD;
#pragma unroll
        for (int i = 0; i < 4; i++) {
            int idx = tid + 256 * i;
            int row = idx >> 3, c = idx & 7;
            CP_ASYNC16(smbase + (uint32_t)(POFF_X0 + row * PSTR + c * 8) * 2,
                       Xc + (size_t)row * DD + c * 8);
            CP_ASYNC16(smbase + (uint32_t)(POFF_W0 + row * PSTR + c * 8) * 2,
                       Wc + (size_t)row * DD + c * 8);
        }
        CP_COMMIT();
    }

    float acc0[8][4], acc1[8][4];
#pragma unroll
    for (int nt = 0; nt < 8; nt++)
#pragma unroll
        for (int c = 0; c < 4; c++) { acc0[nt][c] = 0.0f; acc1[nt][c] = 0.0f; }

    for (int ch = 0; ch < NCH; ch++) {
        int cur = ch & 1;
        if (ch + 1 < NCH) {
            int nb = (ch + 1) & 1;
            const __half* Xc = X + (size_t)rb * DD + (ch + 1) * 64;
            const __half* Wc = Wt + (size_t)cb * DD + (ch + 1) * 64;
#pragma unroll
            for (int i = 0; i < 4; i++) {
                int idx = tid + 256 * i;
                int row = idx >> 3, c = idx & 7;
                CP_ASYNC16(smbase + (uint32_t)((nb ? POFF_X1 : POFF_X0) + row * PSTR + c * 8) * 2,
                           Xc + (size_t)row * DD + c * 8);
                CP_ASYNC16(smbase + (uint32_t)((nb ? POFF_W1 : POFF_W0) + row * PSTR + c * 8) * 2,
                           Wc + (size_t)row * DD + c * 8);
            }
            CP_COMMIT();
            CP_WAIT1();
        } else {
            CP_WAIT0();
        }
        __syncthreads();

        const __half* sX = smh + (cur ? POFF_X1 : POFF_X0);
        const __half* sW = smh + (cur ? POFF_W1 : POFF_W0);

#pragma unroll
        for (int ko = 0; ko < 4; ko++) {
            const __half* x0 = sX + (wr * 32 + gid) * PSTR + 16 * ko + 2 * tig;
            uint32_t a00 = *(const uint32_t*)x0;
            uint32_t a01 = *(const uint32_t*)(x0 + 8 * PSTR);
            uint32_t a02 = *(const uint32_t*)(x0 + 8);
            uint32_t a03 = *(const uint32_t*)(x0 + 8 * PSTR + 8);
            uint32_t a10 = *(const uint32_t*)(x0 + 16 * PSTR);
            uint32_t a11 = *(const uint32_t*)(x0 + 24 * PSTR);
            uint32_t a12 = *(const uint32_t*)(x0 + 16 * PSTR + 8);
            uint32_t a13 = *(const uint32_t*)(x0 + 24 * PSTR + 8);
#pragma unroll
            for (int nt = 0; nt < 8; nt++) {
                const __half* wrow = sW + (wc * 64 + nt * 8 + gid) * PSTR + 16 * ko + 2 * tig;
                uint32_t b0 = *(const uint32_t*)wrow;
                uint32_t b1 = *(const uint32_t*)(wrow + 8);
                mma16(acc0[nt], a00, a01, a02, a03, b0, b1);
                mma16(acc1[nt], a10, a11, a12, a13, b0, b1);
            }
        }
        __syncthreads();
    }

    // epilogue
    const int r0 = rb + wr * 32 + gid;
    const int colbase = cb + wc * 64;
    if (z == 2) {
        // Transposed store for V: Vt[((b*8+h)*64+p)*MM + m]
        const int b_ = rb >> 12;
        const int h_ = colbase >> 6;
        __half* Vtb = Y + ((size_t)(b_ * HH + h_) * PP) * MM;
        const int m0 = r0 & (NN - 1);
#pragma unroll
        for (int nt = 0; nt < 8; nt++) {
            int p = nt * 8 + 2 * tig;
            int col = colbase + p;
            float2 bv2 = *(const float2*)(bias + col);
            Vtb[(size_t)p * MM + m0]            = __float2half(acc0[nt][0] + bv2.x);
            Vtb[(size_t)(p + 1) * MM + m0]      = __float2half(acc0[nt][1] + bv2.y);
            Vtb[(size_t)p * MM + m0 + 8]        = __float2half(acc0[nt][2] + bv2.x);
            Vtb[(size_t)(p + 1) * MM + m0 + 8]  = __float2half(acc0[nt][3] + bv2.y);
            Vtb[(size_t)p * MM + m0 + 16]       = __float2half(acc1[nt][0] + bv2.x);
            Vtb[(size_t)(p + 1) * MM + m0 + 16] = __float2half(acc1[nt][1] + bv2.y);
            Vtb[(size_t)p * MM + m0 + 24]       = __float2half(acc1[nt][2] + bv2.x);
            Vtb[(size_t)(p + 1) * MM + m0 + 24] = __float2half(acc1[nt][3] + bv2.y);
        }
    } else {
#pragma unroll
        for (int nt = 0; nt < 8; nt++) {
            int col = colbase + nt * 8 + 2 * tig;
            float2 bv2 = *(const float2*)(bias + col);
            uint32_t o;
            o = packh2((acc0[nt][0] + bv2.x) * sc, (acc0[nt][1] + bv2.y) * sc);
            *(uint32_t*)(Y + (size_t)r0 * DD + col) = o;
            o = packh2((acc0[nt][2] + bv2.x) * sc, (acc0[nt][3] + bv2.y) * sc);
            *(uint32_t*)(Y + (size_t)(r0 + 8) * DD + col) = o;
            o = packh2((acc1[nt][0] + bv2.x) * sc, (acc1[nt][1] + bv2.y) * sc);
            *(uint32_t*)(Y + (size_t)(r0 + 16) * DD + col) = o;
            o = packh2((acc1[nt][2] + bv2.x) * sc, (acc1[nt][3] + bv2.y) * sc);
            *(uint32_t*)(Y + (size_t)(r0 + 24) * DD + col) = o;
        }
    }
}

// ================= Flash attention: fp16 m16n8k16, Vt d-major =====
// CTA = 128 thr (4 warps), 128 q rows (32/warp), KV tile 64 keys dbl-buffered.
// Base-2 softmax; exp computed in fp16x2 (output = packed PV A-frag directly);
// row-sum l obtained via an extra ones-column MMA (fp32 accumulator fragment).
#define KT    64
#define NTIL  (MM / KT)
#define KSTRH 72
#define ONESH2 0x3C003C00u   // half2 {1,1}

__shared__ __half sKh[2][KT * KSTRH];
__shared__ __half sVt[2][PP * KSTRH];   // [d][key], 64 x 72

// max over this thread's fragment components for one 16-row group + quad reduce
#define GRP_MAX(sarr, i0, i1, outmx) do {                                     \
    float _mx = fmaxf(sarr[0][i0], sarr[0][i1]);                              \
    _Pragma("unroll")                                                         \
    for (int _nt = 1; _nt < 8; _nt++)                                         \
        _mx = fmaxf(_mx, fmaxf(sarr[_nt][i0], sarr[_nt][i1]));                \
    _mx = fmaxf(_mx, __shfl_xor_sync(0xffffffffu, _mx, 1));                   \
    _mx = fmaxf(_mx, __shfl_xor_sync(0xffffffffu, _mx, 2));                   \
    outmx = _mx;                                                              \
} while (0)

__global__ void __launch_bounds__(128, 2) attn_mma_kernel(
    const __half* __restrict__ Q, const __half* __restrict__ K,
    const __half* __restrict__ Vt, float* __restrict__ O)
{
    const int tid  = threadIdx.x;
    const int lane = tid & 31;
    const int w    = tid >> 5;
    const int gid  = lane >> 2;
    const int tig  = lane & 3;

    const int b  = blockIdx.z;
    const int h  = blockIdx.y;
    const int q0 = blockIdx.x * 128;

    const __half* Qb  = Q + ((size_t)(b * NN + q0 + w * 32)) * DD + h * PP;
    const __half* Kb  = K + ((size_t)b * MM) * DD + h * PP;
    const __half* Vtb = Vt + ((size_t)(b * HH + h) * PP) * MM;   // [p][m]

    const uint32_t kb0 = smem_u32(&sKh[0][0]);
    const uint32_t kb1 = smem_u32(&sKh[1][0]);
    const uint32_t vb0 = smem_u32(&sVt[0][0]);
    const uint32_t vb1 = smem_u32(&sVt[1][0]);

#pragma unroll
    for (int i = 0; i < 4; i++) {
        int idx = tid + 128 * i;
        int row = idx >> 3, c = idx & 7;
        CP_ASYNC16(kb0 + (uint32_t)(row * KSTRH + c * 8) * 2,
                   Kb + (size_t)row * DD + c * 8);
        CP_ASYNC16(vb0 + (uint32_t)(row * KSTRH + c * 8) * 2,
                   Vtb + (size_t)row * MM + c * 8);
    }
    CP_COMMIT();

    uint32_t qa0[4][4], qa1[4][4];
#pragma unroll
    for (int ko = 0; ko < 4; ko++) {
        int d0 = 16 * ko + 2 * tig;
        qa0[ko][0] = *(const uint32_t*)(Qb + (size_t)gid * DD + d0);
        qa0[ko][1] = *(const uint32_t*)(Qb + (size_t)(gid + 8) * DD + d0);
        qa0[ko][2] = *(const uint32_t*)(Qb + (size_t)gid * DD + d0 + 8);
        qa0[ko][3] = *(const uint32_t*)(Qb + (size_t)(gid + 8) * DD + d0 + 8);
        qa1[ko][0] = *(const uint32_t*)(Qb + (size_t)(gid + 16) * DD + d0);
        qa1[ko][1] = *(const uint32_t*)(Qb + (size_t)(gid + 24) * DD + d0);
        qa1[ko][2] = *(const uint32_t*)(Qb + (size_t)(gid + 16) * DD + d0 + 8);
        qa1[ko][3] = *(const uint32_t*)(Qb + (size_t)(gid + 24) * DD + d0 + 8);
    }

    float acc0[8][4], acc1[8][4];
    float lacc0[4], lacc1[4];
#pragma unroll
    for (int nt = 0; nt < 8; nt++)
#pragma unroll
        for (int c = 0; c < 4; c++) { acc0[nt][c] = 0.0f; acc1[nt][c] = 0.0f; }
#pragma unroll
    for (int c = 0; c < 4; c++) { lacc0[c] = 0.0f; lacc1[c] = 0.0f; }
    float m00 = -CUDART_INF_F, m01 = -CUDART_INF_F;
    float m10 = -CUDART_INF_F, m11 = -CUDART_INF_F;

    for (int t = 0; t < NTIL; t++) {
        int cur = t & 1;
        if (t + 1 < NTIL) {
            uint32_t kb = (t + 1) & 1 ? kb1 : kb0;
            uint32_t vb = (t + 1) & 1 ? vb1 : vb0;
            const __half* Ks  = Kb + (size_t)(t + 1) * KT * DD;
            const __half* Vts = Vtb + (t + 1) * KT;
#pragma unroll
            for (int i = 0; i < 4; i++) {
                int idx = tid + 128 * i;
                int row = idx >> 3, c = idx & 7;
                CP_ASYNC16(kb + (uint32_t)(row * KSTRH + c * 8) * 2,
                           Ks + (size_t)row * DD + c * 8);
                CP_ASYNC16(vb + (uint32_t)(row * KSTRH + c * 8) * 2,
                           Vts + (size_t)row * MM + c * 8);
            }
            CP_COMMIT();
            CP_WAIT1();
        } else {
            CP_WAIT0();
        }
        __syncthreads();

        const __half* sK = &sKh[cur][0];
        const __half* sV = &sVt[cur][0];

        // --- QK^T ---
        float s0[8][4], s1[8][4];
#pragma unroll
        for (int nt = 0; nt < 8; nt++) {
            s0[nt][0] = s0[nt][1] = s0[nt][2] = s0[nt][3] = 0.0f;
            s1[nt][0] = s1[nt][1] = s1[nt][2] = s1[nt][3] = 0.0f;
            const __half* krow = sK + (nt * 8 + gid) * KSTRH;
#pragma unroll
            for (int ko = 0; ko < 4; ko++) {
                uint32_t b0 = *(const uint32_t*)(krow + 16 * ko + 2 * tig);
                uint32_t b1 = *(const uint32_t*)(krow + 16 * ko + 2 * tig + 8);
                mma16(s0[nt], qa0[ko][0], qa0[ko][1], qa0[ko][2], qa0[ko][3], b0, b1);
                mma16(s1[nt], qa1[ko][0], qa1[ko][1], qa1[ko][2], qa1[ko][3], b0, b1);
            }
        }

        // --- running max + exact rescale-skip ---
        float mx0, mx1, mx2, mx3;
        GRP_MAX(s0, 0, 1, mx0);
        GRP_MAX(s0, 2, 3, mx1);
        GRP_MAX(s1, 0, 1, mx2);
        GRP_MAX(s1, 2, 3, mx3);
        float mn00 = fmaxf(m00, mx0), mn01 = fmaxf(m01, mx1);
        float mn10 = fmaxf(m10, mx2), mn11 = fmaxf(m11, mx3);
        bool chg = (mn00 > m00) | (mn01 > m01) | (mn10 > m10) | (mn11 > m11);
        if (__any_sync(0xffffffffu, chg)) {
            float c00 = exp2f(m00 - mn00), c01 = exp2f(m01 - mn01);
            float c10 = exp2f(m10 - mn10), c11 = exp2f(m11 - mn11);
            lacc0[0] *= c00; lacc0[1] *= c00; lacc0[2] *= c01; lacc0[3] *= c01;
            lacc1[0] *= c10; lacc1[1] *= c10; lacc1[2] *= c11; lacc1[3] *= c11;
#pragma unroll
            for (int nt = 0; nt < 8; nt++) {
                acc0[nt][0] *= c00; acc0[nt][1] *= c00;
                acc0[nt][2] *= c01; acc0[nt][3] *= c01;
                acc1[nt][0] *= c10; acc1[nt][1] *= c10;
                acc1[nt][2] *= c11; acc1[nt][3] *= c11;
            }
        }
        m00 = mn00; m01 = mn01; m10 = mn10; m11 = mn11;

        // --- exp2 in fp16x2: output IS the packed PV A-fragment ---
        // ph[2*nt]   = p rows gid    (group m00/m10), cols 8nt+2tig,+1
        // ph[2*nt+1] = p rows gid+8  (group m01/m11)
        uint32_t ph0[16], ph1[16];
#pragma unroll
        for (int nt = 0; nt < 8; nt++) {
            ph0[2 * nt]     = exph2(s0[nt][0] - m00, s0[nt][1] - m00);
            ph0[2 * nt + 1] = exph2(s0[nt][2] - m01, s0[nt][3] - m01);
            ph1[2 * nt]     = exph2(s1[nt][0] - m10, s1[nt][1] - m10);
            ph1[2 * nt + 1] = exph2(s1[nt][2] - m11, s1[nt][3] - m11);
        }

        // --- PV + l (ones-column MMA) ---
#pragma unroll
        for (int ko = 0; ko < 4; ko++) {
            uint32_t a0 = ph0[4 * ko],     a1 = ph0[4 * ko + 1];
            uint32_t a2 = ph0[4 * ko + 2], a3 = ph0[4 * ko + 3];
            uint32_t c0 = ph1[4 * ko],     c1 = ph1[4 * ko + 1];
            uint32_t c2 = ph1[4 * ko + 2], c3 = ph1[4 * ko + 3];
#pragma unroll
            for (int nt = 0; nt < 8; nt++) {
                const __half* vrow = sV + (nt * 8 + gid) * KSTRH + 16 * ko + 2 * tig;
                uint32_t b0 = *(const uint32_t*)vrow;
                uint32_t b1 = *(const uint32_t*)(vrow + 8);
                mma16(acc0[nt], a0, a1, a2, a3, b0, b1);
                mma16(acc1[nt], c0, c1, c2, c3, b0, b1);
            }
            mma16(lacc0, a0, a1, a2, a3, ONESH2, ONESH2);
            mma16(lacc1, c0, c1, c2, c3, ONESH2, ONESH2);
        }
        __syncthreads();
    }

    // --- normalize & store (l from ones-MMA: rows gid -> [0], gid+8 -> [2]) ---
    float i00 = 1.0f / lacc0[0], i01 = 1.0f / lacc0[2];
    float i10 = 1.0f / lacc1[0], i11 = 1.0f / lacc1[2];
    float* Ob = O + ((size_t)(b * NN + q0 + w * 32)) * DD + h * PP;
#pragma unroll
    for (int nt = 0; nt < 8; nt++) {
        int col = nt * 8 + 2 * tig;
        *(float2*)(Ob + (size_t)gid * DD + col) =
            make_float2(acc0[nt][0] * i00, acc0[nt][1] * i00);
        *(float2*)(Ob + (size_t)(gid + 8) * DD + col) =
            make_float2(acc0[nt][2] * i01, acc0[nt][3] * i01);
        *(float2*)(Ob + (size_t)(gid + 16) * DD + col) =
            make_float2(acc1[nt][0] * i10, acc1[nt][1] * i10);
        *(float2*)(Ob + (size_t)(gid + 24) * DD + col) =
            make_float2(acc1[nt][2] * i11, acc1[nt][3] * i11);
    }
}

// ---------------- launch ----------------
extern "C" void kernel_launch(void* const* d_in, const int* in_sizes, int n_in,
                              void* d_out, int out_size)
{
    const float* queries = (const float*)d_in[0];
    const float* keys    = (const float*)d_in[1];
    const float* values  = (const float*)d_in[2];
    const float* Wq      = (const float*)d_in[3];
    const float* bq      = (const float*)d_in[4];
    const float* Wk      = (const float*)d_in[5];
    const float* bk      = (const float*)d_in[6];
    const float* Wv      = (const float*)d_in[7];
    const float* bv      = (const float*)d_in[8];
    float* out = (float*)d_out;

    __half *pq, *pk, *pvt, *pxq, *pxk, *pxv, *pwq, *pwk, *pwv;
    cudaGetSymbolAddress((void**)&pq,  g_q);
    cudaGetSymbolAddress((void**)&pk,  g_k);
    cudaGetSymbolAddress((void**)&pvt, g_vt);
    cudaGetSymbolAddress((void**)&pxq, g_xq);
    cudaGetSymbolAddress((void**)&pxk, g_xk);
    cudaGetSymbolAddress((void**)&pxv, g_xv);
    cudaGetSymbolAddress((void**)&pwq, g_wqt);
    cudaGetSymbolAddress((void**)&pwk, g_wkt);
    cudaGetSymbolAddress((void**)&pwv, g_wvt);

    const int nX4 = (RR * DD) / 4;
    f2h3_kernel<<<dim3(1024, 1, 3), 256>>>(
        (const float4*)queries, (const float4*)keys, (const float4*)values,
        pxq, pxk, pxv, nX4);
    wt_h3_kernel<<<dim3(DD / 32, DD / 32, 3), dim3(32, 8)>>>(
        Wq, Wk, Wv, pwq, pwk, pwv);

    cudaFuncSetAttribute(proj_mma_kernel,
                         cudaFuncAttributeMaxDynamicSharedMemorySize, PROJ_SMEM_BYTES);
    dim3 pGrid(DD / 128, RR / 128, 3);   // (4, 64, 3)
    proj_mma_kernel<<<pGrid, 256, PROJ_SMEM_BYTES>>>(
        pxq, pxk, pxv, pwq, pwk, pwv, bq, bk, bv, pq, pk, pvt);

    dim3 aGrid(NN / 128, HH, BB);        // (32, 8, 2)
    attn_mma_kernel<<<aGrid, 128>>>(pq, pk, pvt, out);
}